// round 5
// baseline (speedup 1.0000x reference)
#include <cuda_runtime.h>
#include <cuda_bf16.h>
#include <cstdint>

#define T_  256
#define B_  64
#define E_  512
#define H_  512
#define KT  32      // num tags
#define G4  2048    // 4*H
#define TB  (T_*B_)
#define NEGV -100000.0f

typedef __nv_bfloat16 bf16;

// ---------------- scratch ----------------
__device__ __align__(16) bf16  g_x0b[(size_t)TB*E_];      // embedded input bf16 [tb][512]
__device__ __align__(16) bf16  g_x1b[(size_t)TB*2*H_];    // layer0 out bf16 [tb][1024]
__device__ __align__(16) bf16  g_x2b[(size_t)TB*2*H_];    // layer1 out bf16 [tb][1024]
__device__ float g_xp[(size_t)2*T_*G4*B_];                // gates fp32 [d][t][g][b]
__device__ float g_h[(size_t)2*H_*B_];                    // recurrent h fp32 [d][k][b]
__device__ __align__(16) bf16  g_wih0b[(size_t)2*G4*E_];
__device__ __align__(16) bf16  g_wih1b[(size_t)2*G4*2*H_];
__device__ float g_feats[(size_t)TB*KT];
__device__ float g_part[B_];
__device__ unsigned g_bar_cnt[2];
__device__ unsigned g_bar_gen[2];

// ---------------- helpers ----------------
__device__ __forceinline__ float tf32r(float x) {
    float r;
    asm("cvt.rna.tf32.f32 %0, %1;" : "=f"(r) : "f"(x));
    return r;
}

__device__ __forceinline__ void mma_tf32(float* c,
    float a0, float a1, float a2, float a3, float b0, float b1)
{
    uint32_t A0 = __float_as_uint(a0), A1 = __float_as_uint(a1);
    uint32_t A2 = __float_as_uint(a2), A3 = __float_as_uint(a3);
    uint32_t B0 = __float_as_uint(b0), B1 = __float_as_uint(b1);
    asm volatile(
        "mma.sync.aligned.m16n8k8.row.col.f32.tf32.tf32.f32 "
        "{%0,%1,%2,%3},{%4,%5,%6,%7},{%8,%9},{%0,%1,%2,%3};"
        : "+f"(c[0]), "+f"(c[1]), "+f"(c[2]), "+f"(c[3])
        : "r"(A0), "r"(A1), "r"(A2), "r"(A3), "r"(B0), "r"(B1));
}

__device__ __forceinline__ void mma_bf(float* c, uint32_t a0, uint32_t a1,
                                       uint32_t a2, uint32_t a3,
                                       uint32_t b0, uint32_t b1)
{
    asm volatile(
        "mma.sync.aligned.m16n8k16.row.col.f32.bf16.bf16.f32 "
        "{%0,%1,%2,%3},{%4,%5,%6,%7},{%8,%9},{%0,%1,%2,%3};"
        : "+f"(c[0]), "+f"(c[1]), "+f"(c[2]), "+f"(c[3])
        : "r"(a0), "r"(a1), "r"(a2), "r"(a3), "r"(b0), "r"(b1));
}

__device__ __forceinline__ float sigf(float x) {
    return 1.f / (1.f + __expf(-x));
}

// grid barrier among the 64 blocks of one direction (round-1 proven)
__device__ __forceinline__ void gbarrier(int d) {
    __syncthreads();
    if (threadIdx.x == 0) {
        __threadfence();
        unsigned g = atomicAdd(&g_bar_gen[d], 0u);
        unsigned a = atomicAdd(&g_bar_cnt[d], 1u);
        if (a == 63u) {
            atomicExch(&g_bar_cnt[d], 0u);
            __threadfence();
            atomicExch(&g_bar_gen[d], g + 1u);
        } else {
            while (atomicAdd(&g_bar_gen[d], 0u) == g) { __nanosleep(64); }
        }
        __threadfence();
    }
    __syncthreads();
}

// ---------------- weight conversion fp32 -> bf16 (wih only) ----------------
__global__ void cvt_k(const float* __restrict__ wih0, const float* __restrict__ wih1) {
    int i = blockIdx.x * 256 + threadIdx.x;   // float4 index
    const float* s; bf16* dst; int off;
    if (i < 524288)       { s = wih0; dst = g_wih0b; off = i; }
    else if (i < 1572864) { s = wih1; dst = g_wih1b; off = i - 524288; }
    else return;
    float4 v = ((const float4*)s)[off];
    __nv_bfloat162* o = (__nv_bfloat162*)dst + (size_t)off * 2;
    o[0] = __floats2bfloat162_rn(v.x, v.y);
    o[1] = __floats2bfloat162_rn(v.z, v.w);
}

// ---------------- embedding lookup -> bf16 ----------------
__global__ void embed_k(const int* __restrict__ tokens, const float* __restrict__ embed) {
    size_t i = (size_t)blockIdx.x * 256 + threadIdx.x;  // float4 index
    size_t el = i * 4;
    size_t tb = el >> 9;
    int    e  = (int)(el & 511);
    float4 v = *(const float4*)(embed + (size_t)tokens[tb] * E_ + e);
    __nv_bfloat162* o = (__nv_bfloat162*)(g_x0b + el);
    o[0] = __floats2bfloat162_rn(v.x, v.y);
    o[1] = __floats2bfloat162_rn(v.z, v.w);
}

// ---------------- input projection GEMM (bf16): xp[d][t][g][b] ------------------
// round-1 structure: M=128 g-rows x N=64 (one timestep) per block, K-chunk 32
template<int L>
__global__ __launch_bounds__(256) void gemm_xp_k(const bf16* __restrict__ Wb,
                                                 const float* __restrict__ bias)
{
    constexpr int KSZ = (L == 0) ? 512 : 1024;
    const bf16* X = (L == 0) ? g_x0b : g_x1b;

    __shared__ __align__(16) bf16 As[128][40];
    __shared__ __align__(16) bf16 Bs[64][40];

    const int d = blockIdx.z, t = blockIdx.y, gbase = blockIdx.x * 128;
    const bf16* Wd = Wb + (size_t)d * G4 * KSZ;
    const bf16* Xt = X + (size_t)t * B_ * KSZ;

    const int tid = threadIdx.x, warp = tid >> 5, lane = tid & 31;
    const int wm = (warp & 3) * 32, wn = (warp >> 2) * 32;
    const int gid = lane >> 2, tig = lane & 3;

    float acc[2][4][4] = {};

    const int srow = tid >> 2;
    const int c8   = (tid & 3) * 8;

    for (int k0 = 0; k0 < KSZ; k0 += 32) {
#pragma unroll
        for (int p = 0; p < 2; p++)
            *(uint4*)&As[srow + p * 64][c8] =
                *(const uint4*)(Wd + (size_t)(gbase + srow + p * 64) * KSZ + k0 + c8);
        *(uint4*)&Bs[srow][c8] = *(const uint4*)(Xt + (size_t)srow * KSZ + k0 + c8);
        __syncthreads();
#pragma unroll
        for (int ks = 0; ks < 2; ks++) {
            const int kk = ks * 16 + 2 * tig;
            uint32_t a[2][4];
#pragma unroll
            for (int mt = 0; mt < 2; mt++) {
                int r0 = wm + mt * 16 + gid;
                a[mt][0] = *(const uint32_t*)&As[r0][kk];
                a[mt][1] = *(const uint32_t*)&As[r0 + 8][kk];
                a[mt][2] = *(const uint32_t*)&As[r0][kk + 8];
                a[mt][3] = *(const uint32_t*)&As[r0 + 8][kk + 8];
            }
#pragma unroll
            for (int nt = 0; nt < 4; nt++) {
                int ci = wn + nt * 8 + gid;
                uint32_t b0 = *(const uint32_t*)&Bs[ci][kk];
                uint32_t b1 = *(const uint32_t*)&Bs[ci][kk + 8];
                mma_bf(acc[0][nt], a[0][0], a[0][1], a[0][2], a[0][3], b0, b1);
                mma_bf(acc[1][nt], a[1][0], a[1][1], a[1][2], a[1][3], b0, b1);
            }
        }
        __syncthreads();
    }
    // epilogue: + bias, write xp[d][t][g][b]
    float* XP = g_xp + ((size_t)(d * T_ + t) * G4) * B_;
#pragma unroll
    for (int mt = 0; mt < 2; mt++) {
        int r0 = gbase + wm + mt * 16 + gid;
        float bb0 = bias[(size_t)d * G4 + r0];
        float bb1 = bias[(size_t)d * G4 + r0 + 8];
#pragma unroll
        for (int nt = 0; nt < 4; nt++) {
            int c = wn + nt * 8 + tig * 2;
            *(float2*)(XP + (size_t)r0 * B_ + c) =
                make_float2(acc[mt][nt][0] + bb0, acc[mt][nt][1] + bb0);
            *(float2*)(XP + (size_t)(r0 + 8) * B_ + c) =
                make_float2(acc[mt][nt][2] + bb1, acc[mt][nt][3] + bb1);
        }
    }
}

// ---------------- recurrence kernel (round-1 proven, k-chunk 128) ----------------
// grid = 128 blocks (0-63 fwd, 64-127 bwd), 256 threads, 8 h-cols per block.
// smem: whh 32x516 + h 128x68 + z 32x68 floats = 109568 B
#define REC_SMEM ((32 * 516 + 128 * 68 + 32 * 68) * 4)

template<int L>
__global__ __launch_bounds__(256, 1) void lstm_rec_k(const float* __restrict__ Whh)
{
    bf16* Xout = (L == 0) ? g_x1b : g_x2b;
    extern __shared__ float sm[];
    float* whh_s = sm;                  // [32][516]
    float* h_s   = sm + 32 * 516;       // [128][68]
    float* z_s   = h_s + 128 * 68;      // [32][68]

    const int blk = blockIdx.x;
    const int d = blk >> 6;
    const int jbase = (blk & 63) * 8;
    const int tid = threadIdx.x, warp = tid >> 5, lane = tid & 31;
    const int gid = lane >> 2, tig = lane & 3;
    const int wm = (warp >> 2) * 16, wn = (warp & 3) * 16;

    const float* Wd = Whh + (size_t)d * G4 * H_;

    // load this block's 32 Whh rows (local m = q*8 + jl <-> global q*512 + jbase + jl)
    for (int i = tid; i < 32 * 128; i += 256) {
        int m = i >> 7, c4 = (i & 127) * 4;
        int grow = (m >> 3) * 512 + jbase + (m & 7);
        float4 v = *(const float4*)(Wd + (size_t)grow * H_ + c4);
        float4 o; o.x = tf32r(v.x); o.y = tf32r(v.y); o.z = tf32r(v.z); o.w = tf32r(v.w);
        *(float4*)&whh_s[m * 516 + c4] = o;
    }

    // per-thread cell state: pairs (jl, bb) and (jl, bb+1)
    const int p = tid * 2;
    const int jl = p >> 6;
    const int bb = p & 63;
    const int jglob = jbase + jl;
    float cst[2] = {0.f, 0.f};

    g_h[((size_t)d * H_ + jglob) * B_ + bb]     = 0.f;
    g_h[((size_t)d * H_ + jglob) * B_ + bb + 1] = 0.f;

    gbarrier(d);

    for (int s = 0; s < T_; s++) {
        const int t = (d == 0) ? s : (T_ - 1 - s);
        float z[2][4] = {{0.f,0.f,0.f,0.f},{0.f,0.f,0.f,0.f}};

        for (int kc = 0; kc < 4; kc++) {
            // stage 128x64 h chunk
#pragma unroll
            for (int pp = 0; pp < 8; pp++) {
                int u = pp * 256 + tid;
                int kl = u >> 4;
                int b4 = (u & 15) * 4;
                float4 v = *(const float4*)(g_h + ((size_t)d * H_ + kc * 128 + kl) * B_ + b4);
                *(float4*)&h_s[kl * 68 + b4] = v;
            }
            __syncthreads();
#pragma unroll
            for (int ks = 0; ks < 16; ks++) {
                const int ko = ks * 8;
                const int ar = wm + gid;
                const int kcol = kc * 128 + ko;
                float a0 = whh_s[ar * 516 + kcol + tig];
                float a1 = whh_s[(ar + 8) * 516 + kcol + tig];
                float a2 = whh_s[ar * 516 + kcol + tig + 4];
                float a3 = whh_s[(ar + 8) * 516 + kcol + tig + 4];
#pragma unroll
                for (int nt = 0; nt < 2; nt++) {
                    int nc = wn + nt * 8 + gid;
                    float b0 = h_s[(ko + tig) * 68 + nc];
                    float b1 = h_s[(ko + tig + 4) * 68 + nc];
                    mma_tf32(z[nt], a0, a1, a2, a3, b0, b1);
                }
            }
            __syncthreads();
        }
        // write z fragments to smem
#pragma unroll
        for (int nt = 0; nt < 2; nt++) {
            int cc = wn + nt * 8 + tig * 2;
            *(float2*)&z_s[(wm + gid) * 68 + cc]     = make_float2(z[nt][0], z[nt][1]);
            *(float2*)&z_s[(wm + gid + 8) * 68 + cc] = make_float2(z[nt][2], z[nt][3]);
        }
        __syncthreads();

        // gates + state update for (jl, bb), (jl, bb+1)
        const float* xpb = g_xp + ((size_t)(d * T_ + t) * G4 + jbase + jl) * B_;
#pragma unroll
        for (int u = 0; u < 2; u++) {
            int b = bb + u;
            float zi = z_s[(jl)      * 68 + b] + xpb[0 * H_ * B_ + b];
            float zf = z_s[(8 + jl)  * 68 + b] + xpb[1 * H_ * B_ + b];
            float zg = z_s[(16 + jl) * 68 + b] + xpb[2 * H_ * B_ + b];
            float zo = z_s[(24 + jl) * 68 + b] + xpb[3 * H_ * B_ + b];
            float iv = sigf(zi), fv = sigf(zf), ov = sigf(zo);
            float gv = tanhf(zg);
            cst[u] = fv * cst[u] + iv * gv;
            float h = ov * tanhf(cst[u]);
            g_h[((size_t)d * H_ + jglob) * B_ + b] = tf32r(h);
            Xout[((size_t)t * B_ + b) * (2 * H_) + d * H_ + jglob] = __float2bfloat16(h);
        }
        gbarrier(d);
    }
}

// ---------------- emission scores ----------------
__global__ __launch_bounds__(256) void feats_k(const float* __restrict__ lw,
                                               const float* __restrict__ lb)
{
    __shared__ float xs[8][129];
    __shared__ float ws[32][129];
    const int tid = threadIdx.x;
    const int r = tid >> 5, k = tid & 31;
    const size_t tb0 = (size_t)blockIdx.x * 8;
    float acc = 0.f;
    for (int c0 = 0; c0 < 2 * H_; c0 += 128) {
        for (int i = tid; i < 8 * 128; i += 256)
            xs[i >> 7][i & 127] =
                __bfloat162float(g_x2b[(tb0 + (i >> 7)) * (2 * H_) + c0 + (i & 127)]);
        for (int i = tid; i < 32 * 128; i += 256)
            ws[i >> 7][i & 127] = lw[(size_t)(i >> 7) * (2 * H_) + c0 + (i & 127)];
        __syncthreads();
#pragma unroll 16
        for (int kk = 0; kk < 128; kk++) acc += xs[r][kk] * ws[k][kk];
        __syncthreads();
    }
    g_feats[(tb0 + r) * KT + k] = acc + lb[k];
}

// ---------------- CRF: one warp per batch element ----------------
__global__ void crf_k(const int* __restrict__ tokens, const int* __restrict__ tags,
                      const int* __restrict__ lengths, const float* __restrict__ trans)
{
    const int b = blockIdx.x;
    const int k = threadIdx.x;              // 0..31
    __shared__ float al[KT];

    float tr[KT];
#pragma unroll
    for (int j = 0; j < KT; j++) tr[j] = trans[k * KT + j];

    al[k] = (k == 30) ? 0.f : NEGV;
    __syncwarp();

    for (int t = 0; t < T_; t++) {
        float m = -3.4e38f;
#pragma unroll
        for (int j = 0; j < KT; j++) m = fmaxf(m, al[j] + tr[j]);
        float ss = 0.f;
#pragma unroll
        for (int j = 0; j < KT; j++) ss += __expf(al[j] + tr[j] - m);
        float nw = m + __logf(ss) + g_feats[((size_t)t * B_ + b) * KT + k];
        int msk = tokens[t * B_ + b] > 0;
        __syncwarp();
        if (msk) al[k] = nw;
        __syncwarp();
    }

    float v = al[k] + trans[31 * KT + k];
    float m = v;
#pragma unroll
    for (int o = 16; o; o >>= 1) m = fmaxf(m, __shfl_xor_sync(0xffffffffu, m, o));
    float e = __expf(v - m);
#pragma unroll
    for (int o = 16; o; o >>= 1) e += __shfl_xor_sync(0xffffffffu, e, o);
    float logz = m + __logf(e);

    float gl = 0.f;
    for (int t = k; t < T_; t += 32) {
        int cur  = tags[t * B_ + b];
        int prev = (t == 0) ? 30 : tags[(t - 1) * B_ + b];
        float mm = (tokens[t * B_ + b] > 0) ? 1.f : 0.f;
        gl += mm * (trans[cur * KT + prev] + g_feats[((size_t)t * B_ + b) * KT + cur]);
    }
#pragma unroll
    for (int o = 16; o; o >>= 1) gl += __shfl_xor_sync(0xffffffffu, gl, o);
    gl += trans[31 * KT + tags[(T_ - 1) * B_ + b]];

    if (k == 0) g_part[b] = (logz - gl) / (float)lengths[b];
}

__global__ void out_k(float* __restrict__ out) {
    __shared__ float s[B_];
    s[threadIdx.x] = g_part[threadIdx.x];
    __syncthreads();
    for (int o = 32; o; o >>= 1) {
        if (threadIdx.x < o) s[threadIdx.x] += s[threadIdx.x + o];
        __syncthreads();
    }
    if (threadIdx.x == 0) out[0] = s[0];
}

// ---------------- launcher ----------------
extern "C" void kernel_launch(void* const* d_in, const int* in_sizes, int n_in,
                              void* d_out, int out_size)
{
    const int*   tokens  = (const int*)d_in[0];
    const int*   tags    = (const int*)d_in[1];
    const int*   lengths = (const int*)d_in[2];
    const float* embed   = (const float*)d_in[3];
    const float* wih0    = (const float*)d_in[4];
    const float* whh0    = (const float*)d_in[5];
    const float* b0      = (const float*)d_in[6];
    const float* wih1    = (const float*)d_in[7];
    const float* whh1    = (const float*)d_in[8];
    const float* b1      = (const float*)d_in[9];
    const float* lin_w   = (const float*)d_in[10];
    const float* lin_b   = (const float*)d_in[11];
    const float* trans   = (const float*)d_in[12];
    float* out = (float*)d_out;

    cudaFuncSetAttribute(lstm_rec_k<0>, cudaFuncAttributeMaxDynamicSharedMemorySize, REC_SMEM);
    cudaFuncSetAttribute(lstm_rec_k<1>, cudaFuncAttributeMaxDynamicSharedMemorySize, REC_SMEM);

    cvt_k<<<6144, 256>>>(wih0, wih1);
    embed_k<<<8192, 256>>>(tokens, embed);

    gemm_xp_k<0><<<dim3(16, 256, 2), 256>>>(g_wih0b, b0);
    lstm_rec_k<0><<<128, 256, REC_SMEM>>>(whh0);

    gemm_xp_k<1><<<dim3(16, 256, 2), 256>>>(g_wih1b, b1);
    lstm_rec_k<1><<<128, 256, REC_SMEM>>>(whh1);

    feats_k<<<TB / 8, 256>>>(lin_w, lin_b);
    crf_k<<<B_, 32>>>(tokens, tags, lengths, trans);
    out_k<<<1, B_>>>(out);
}

// round 6
// speedup vs baseline: 2.9646x; 2.9646x over previous
#include <cuda_runtime.h>
#include <cuda_bf16.h>
#include <cstdint>

#define T_  256
#define B_  64
#define E_  512
#define H_  512
#define KT  32      // num tags
#define G4  2048    // 4*H
#define NEGV -100000.0f

// ---------------- scratch (static device allocations are allowed) ----------------
__device__ float g_x0[(size_t)T_*B_*E_];          // embedded input, tf32-rounded
__device__ float g_xp[(size_t)2*T_*G4*B_];        // input-proj gates  [d][t][g][b]
__device__ float g_x1[(size_t)T_*B_*2*H_];        // layer0 output [tb][1024]
__device__ float g_x2[(size_t)T_*B_*2*H_];        // layer1 output
__device__ float g_h[(size_t)2*H_*B_];            // recurrent h state [d][k][b]
__device__ float g_feats[(size_t)T_*B_*KT];       // emission scores
__device__ float g_part[B_];
__device__ unsigned g_bar_cnt[2];
__device__ unsigned g_bar_gen[2];

// ---------------- helpers ----------------
__device__ __forceinline__ float tf32r(float x) {
    float r;
    asm("cvt.rna.tf32.f32 %0, %1;" : "=f"(r) : "f"(x));
    return r;
}

__device__ __forceinline__ void mma_tf32(float* c,
    float a0, float a1, float a2, float a3, float b0, float b1)
{
    uint32_t A0 = __float_as_uint(a0), A1 = __float_as_uint(a1);
    uint32_t A2 = __float_as_uint(a2), A3 = __float_as_uint(a3);
    uint32_t B0 = __float_as_uint(b0), B1 = __float_as_uint(b1);
    asm volatile(
        "mma.sync.aligned.m16n8k8.row.col.f32.tf32.tf32.f32 "
        "{%0,%1,%2,%3},{%4,%5,%6,%7},{%8,%9},{%0,%1,%2,%3};"
        : "+f"(c[0]), "+f"(c[1]), "+f"(c[2]), "+f"(c[3])
        : "r"(A0), "r"(A1), "r"(A2), "r"(A3), "r"(B0), "r"(B1));
}

__device__ __forceinline__ void cpa16(uint32_t dst, const void* src) {
    asm volatile("cp.async.cg.shared.global [%0], [%1], 16;" :: "r"(dst), "l"(src));
}
#define CP_COMMIT asm volatile("cp.async.commit_group;")
#define CP_WAIT(n) asm volatile("cp.async.wait_group %0;" :: "n"(n))

__device__ __forceinline__ float sigf(float x) {
    return 1.f / (1.f + __expf(-x));
}

// grid barrier among the 64 blocks of one direction (round-1 proven)
__device__ __forceinline__ void gbarrier(int d) {
    __syncthreads();
    if (threadIdx.x == 0) {
        __threadfence();
        unsigned g = atomicAdd(&g_bar_gen[d], 0u);
        unsigned a = atomicAdd(&g_bar_cnt[d], 1u);
        if (a == 63u) {
            atomicExch(&g_bar_cnt[d], 0u);
            __threadfence();
            atomicExch(&g_bar_gen[d], g + 1u);
        } else {
            while (atomicAdd(&g_bar_gen[d], 0u) == g) { __nanosleep(64); }
        }
        __threadfence();
    }
    __syncthreads();
}

// ---------------- embedding lookup ----------------
__global__ void embed_k(const int* __restrict__ tokens, const float* __restrict__ embed) {
    size_t i = (size_t)blockIdx.x * blockDim.x + threadIdx.x;   // float4 index
    if (i >= (size_t)T_ * B_ * E_ / 4) return;
    size_t el = i * 4;
    size_t tb = el / E_;
    int    e  = (int)(el % E_);
    const float4 v = *(const float4*)(embed + (size_t)tokens[tb] * E_ + e);
    float4 o;
    o.x = tf32r(v.x); o.y = tf32r(v.y); o.z = tf32r(v.z); o.w = tf32r(v.w);
    *(float4*)(g_x0 + el) = o;
}

// ---------------- input projection GEMM: xp[d][t][g][b] = W[d] @ X^T + bias ------
// (round-1 verbatim) M=2048 (g), N=64 per block (one timestep)
template<int L>
__global__ __launch_bounds__(256) void gemm_xp_k(const float* __restrict__ W,
                                                 const float* __restrict__ bias)
{
    constexpr int KSZ = (L == 0) ? 512 : 1024;
    const float* X = (L == 0) ? g_x0 : g_x1;

    __shared__ float As[128][36];
    __shared__ float Bs[64][36];

    const int d = blockIdx.z, t = blockIdx.y, gbase = blockIdx.x * 128;
    const float* Wd = W + (size_t)d * G4 * KSZ;
    const float* Xt = X + (size_t)t * B_ * KSZ;

    const int tid = threadIdx.x, warp = tid >> 5, lane = tid & 31;
    const int wm = (warp >> 1) * 32, wn = (warp & 1) * 32;
    const int gid = lane >> 2, tig = lane & 3;

    float acc[2][4][4];
#pragma unroll
    for (int a = 0; a < 2; a++)
#pragma unroll
        for (int b = 0; b < 4; b++)
#pragma unroll
            for (int c = 0; c < 4; c++) acc[a][b][c] = 0.f;

    const int r  = tid >> 3;
    const int kv = (tid & 7) * 4;

    for (int k0 = 0; k0 < KSZ; k0 += 32) {
#pragma unroll
        for (int p = 0; p < 4; p++) {
            float4 v = *(const float4*)(Wd + (size_t)(gbase + r + p * 32) * KSZ + k0 + kv);
            float4 o; o.x = tf32r(v.x); o.y = tf32r(v.y); o.z = tf32r(v.z); o.w = tf32r(v.w);
            *(float4*)&As[r + p * 32][kv] = o;
        }
#pragma unroll
        for (int p = 0; p < 2; p++) {
            float4 v = *(const float4*)(Xt + (size_t)(r + p * 32) * KSZ + k0 + kv);
            float4 o; o.x = tf32r(v.x); o.y = tf32r(v.y); o.z = tf32r(v.z); o.w = tf32r(v.w);
            *(float4*)&Bs[r + p * 32][kv] = o;
        }
        __syncthreads();
#pragma unroll
        for (int ks = 0; ks < 4; ks++) {
            const int ko = ks * 8;
            float a[2][4];
#pragma unroll
            for (int mt = 0; mt < 2; mt++) {
                int r0 = wm + mt * 16 + gid;
                a[mt][0] = As[r0][ko + tig];
                a[mt][1] = As[r0 + 8][ko + tig];
                a[mt][2] = As[r0][ko + tig + 4];
                a[mt][3] = As[r0 + 8][ko + tig + 4];
            }
#pragma unroll
            for (int nt = 0; nt < 4; nt++) {
                int ci = wn + nt * 8 + gid;
                float b0 = Bs[ci][ko + tig];
                float b1 = Bs[ci][ko + tig + 4];
                mma_tf32(acc[0][nt], a[0][0], a[0][1], a[0][2], a[0][3], b0, b1);
                mma_tf32(acc[1][nt], a[1][0], a[1][1], a[1][2], a[1][3], b0, b1);
            }
        }
        __syncthreads();
    }
    // epilogue: + bias, write xp[d][t][g][b]
    float* XP = g_xp + ((size_t)(d * T_ + t) * G4) * B_;
#pragma unroll
    for (int mt = 0; mt < 2; mt++) {
        int r0 = gbase + wm + mt * 16 + gid;
        float bb0 = bias[(size_t)d * G4 + r0];
        float bb1 = bias[(size_t)d * G4 + r0 + 8];
#pragma unroll
        for (int nt = 0; nt < 4; nt++) {
            int c = wn + nt * 8 + tig * 2;
            float2 v0 = make_float2(acc[mt][nt][0] + bb0, acc[mt][nt][1] + bb0);
            float2 v1 = make_float2(acc[mt][nt][2] + bb1, acc[mt][nt][3] + bb1);
            *(float2*)(XP + (size_t)r0 * B_ + c)       = v0;
            *(float2*)(XP + (size_t)(r0 + 8) * B_ + c) = v1;
        }
    }
}

// ---------------- recurrence kernel ----------------
// round-1 structure; ONE change: h-chunk staging is double-buffered cp.async,
// plus xp gate loads hoisted to step start. Math order bit-identical to round 1.
// smem: whh 32x516 + h 2x64x68 + z 32x68 floats = 109568 B
#define REC_SMEM ((32 * 516 + 2 * 64 * 68 + 32 * 68) * 4)

template<int L>
__global__ __launch_bounds__(256, 1) void lstm_rec_k(const float* __restrict__ Whh)
{
    float* Xout = (L == 0) ? g_x1 : g_x2;
    extern __shared__ float sm[];
    float* whh_s = sm;                       // [32][516]
    float* h_s   = sm + 32 * 516;            // [2][64][68]
    float* z_s   = sm + 32 * 516 + 2 * 64 * 68; // [32][68]
    const uint32_t h_sa = (uint32_t)__cvta_generic_to_shared(h_s);

    const int blk = blockIdx.x;
    const int d = blk >> 6;
    const int jbase = (blk & 63) * 8;
    const int tid = threadIdx.x, warp = tid >> 5, lane = tid & 31;
    const int gid = lane >> 2, tig = lane & 3;
    const int wm = (warp >> 2) * 16, wn = (warp & 3) * 16;

    const float* Wd = Whh + (size_t)d * G4 * H_;

    // load this block's 32 Whh rows (local m = q*8 + jl <-> global q*512 + jbase + jl)
    for (int i = tid; i < 32 * 128; i += 256) {
        int m = i >> 7, c4 = (i & 127) * 4;
        int grow = (m >> 3) * 512 + jbase + (m & 7);
        float4 v = *(const float4*)(Wd + (size_t)grow * H_ + c4);
        float4 o; o.x = tf32r(v.x); o.y = tf32r(v.y); o.z = tf32r(v.z); o.w = tf32r(v.w);
        *(float4*)&whh_s[m * 516 + c4] = o;
    }

    // per-thread cell state: pairs (jl, bb) and (jl, bb+1)
    const int p = tid * 2;
    const int jl = p >> 6;
    const int bb = p & 63;
    const int jglob = jbase + jl;
    float cst[2] = {0.f, 0.f};

    g_h[((size_t)d * H_ + jglob) * B_ + bb]     = 0.f;
    g_h[((size_t)d * H_ + jglob) * B_ + bb + 1] = 0.f;

    gbarrier(d);

    const float* hsrc = g_h + (size_t)d * H_ * B_;
    const int skl = tid >> 4;            // staging row within quarter (0..15)+16p
    const int sb4 = (tid & 15) * 4;      // staging col (float4)

    for (int s = 0; s < T_; s++) {
        const int t = (d == 0) ? s : (T_ - 1 - s);

        // hoisted xp gate loads (independent of the pipeline below)
        const float* xpb = g_xp + ((size_t)(d * T_ + t) * G4 + jbase + jl) * B_;
        float xv[2][4];
#pragma unroll
        for (int u = 0; u < 2; u++) {
            int b = bb + u;
            xv[u][0] = xpb[0 * H_ * B_ + b];
            xv[u][1] = xpb[1 * H_ * B_ + b];
            xv[u][2] = xpb[2 * H_ * B_ + b];
            xv[u][3] = xpb[3 * H_ * B_ + b];
        }

        float z[2][4] = {{0.f,0.f,0.f,0.f},{0.f,0.f,0.f,0.f}};

        // prologue: stage chunk 0 into buffer 0
#pragma unroll
        for (int pp = 0; pp < 4; pp++) {
            int kl = skl + pp * 16;
            cpa16(h_sa + (kl * 68 + sb4) * 4, hsrc + (size_t)kl * B_ + sb4);
        }
        CP_COMMIT;

        for (int kc = 0; kc < 8; kc++) {
            if (kc + 1 < 8) {
                const int buf = (kc + 1) & 1;
#pragma unroll
                for (int pp = 0; pp < 4; pp++) {
                    int kl = skl + pp * 16;
                    cpa16(h_sa + (buf * 64 * 68 + kl * 68 + sb4) * 4,
                          hsrc + (size_t)((kc + 1) * 64 + kl) * B_ + sb4);
                }
                CP_COMMIT;
                CP_WAIT(1);
            } else {
                CP_WAIT(0);
            }
            __syncthreads();

            const float* hb = h_s + (kc & 1) * 64 * 68;
#pragma unroll
            for (int ks = 0; ks < 8; ks++) {
                const int ko = ks * 8;
                const int ar = wm + gid;
                const int kcol = kc * 64 + ko;
                float a0 = whh_s[ar * 516 + kcol + tig];
                float a1 = whh_s[(ar + 8) * 516 + kcol + tig];
                float a2 = whh_s[ar * 516 + kcol + tig + 4];
                float a3 = whh_s[(ar + 8) * 516 + kcol + tig + 4];
#pragma unroll
                for (int nt = 0; nt < 2; nt++) {
                    int nc = wn + nt * 8 + gid;
                    float b0 = hb[(ko + tig) * 68 + nc];
                    float b1 = hb[(ko + tig + 4) * 68 + nc];
                    mma_tf32(z[nt], a0, a1, a2, a3, b0, b1);
                }
            }
            __syncthreads();
        }
        // write z fragments to smem
#pragma unroll
        for (int nt = 0; nt < 2; nt++) {
            int cc = wn + nt * 8 + tig * 2;
            *(float2*)&z_s[(wm + gid) * 68 + cc]     = make_float2(z[nt][0], z[nt][1]);
            *(float2*)&z_s[(wm + gid + 8) * 68 + cc] = make_float2(z[nt][2], z[nt][3]);
        }
        __syncthreads();

        // gates + state update for (jl, bb), (jl, bb+1)
#pragma unroll
        for (int u = 0; u < 2; u++) {
            int b = bb + u;
            float zi = z_s[(jl)      * 68 + b] + xv[u][0];
            float zf = z_s[(8 + jl)  * 68 + b] + xv[u][1];
            float zg = z_s[(16 + jl) * 68 + b] + xv[u][2];
            float zo = z_s[(24 + jl) * 68 + b] + xv[u][3];
            float iv = sigf(zi), fv = sigf(zf), ov = sigf(zo);
            float gv = tanhf(zg);
            cst[u] = fv * cst[u] + iv * gv;
            float h = ov * tanhf(cst[u]);
            float hc = tf32r(h);
            g_h[((size_t)d * H_ + jglob) * B_ + b] = hc;
            Xout[((size_t)t * B_ + b) * (2 * H_) + d * H_ + jglob] = hc;
        }
        gbarrier(d);
    }
}

// ---------------- emission scores (round-1 verbatim) ----------------
__global__ __launch_bounds__(256) void feats_k(const float* __restrict__ lw,
                                               const float* __restrict__ lb)
{
    __shared__ float xs[8][129];
    __shared__ float ws[32][129];
    const int tid = threadIdx.x;
    const int r = tid >> 5, k = tid & 31;
    const size_t tb0 = (size_t)blockIdx.x * 8;
    float acc = 0.f;
    for (int c0 = 0; c0 < 2 * H_; c0 += 128) {
        for (int i = tid; i < 8 * 128; i += 256)
            xs[i >> 7][i & 127] = g_x2[(tb0 + (i >> 7)) * (2 * H_) + c0 + (i & 127)];
        for (int i = tid; i < 32 * 128; i += 256)
            ws[i >> 7][i & 127] = lw[(size_t)(i >> 7) * (2 * H_) + c0 + (i & 127)];
        __syncthreads();
#pragma unroll 16
        for (int kk = 0; kk < 128; kk++) acc += xs[r][kk] * ws[k][kk];
        __syncthreads();
    }
    g_feats[(tb0 + r) * KT + k] = acc + lb[k];
}

// ---------------- CRF (round-1 verbatim) ----------------
__global__ void crf_k(const int* __restrict__ tokens, const int* __restrict__ tags,
                      const int* __restrict__ lengths, const float* __restrict__ trans)
{
    const int b = blockIdx.x;
    const int k = threadIdx.x;              // 0..31
    __shared__ float al[KT];

    float tr[KT];
#pragma unroll
    for (int j = 0; j < KT; j++) tr[j] = trans[k * KT + j];

    al[k] = (k == 30) ? 0.f : NEGV;
    __syncwarp();

    for (int t = 0; t < T_; t++) {
        float m = -3.4e38f;
#pragma unroll
        for (int j = 0; j < KT; j++) m = fmaxf(m, al[j] + tr[j]);
        float ss = 0.f;
#pragma unroll
        for (int j = 0; j < KT; j++) ss += __expf(al[j] + tr[j] - m);
        float nw = m + __logf(ss) + g_feats[((size_t)t * B_ + b) * KT + k];
        int msk = tokens[t * B_ + b] > 0;
        __syncwarp();
        if (msk) al[k] = nw;
        __syncwarp();
    }

    float v = al[k] + trans[31 * KT + k];
    float m = v;
#pragma unroll
    for (int o = 16; o; o >>= 1) m = fmaxf(m, __shfl_xor_sync(0xffffffffu, m, o));
    float e = __expf(v - m);
#pragma unroll
    for (int o = 16; o; o >>= 1) e += __shfl_xor_sync(0xffffffffu, e, o);
    float logz = m + __logf(e);

    float gl = 0.f;
    for (int t = k; t < T_; t += 32) {
        int cur  = tags[t * B_ + b];
        int prev = (t == 0) ? 30 : tags[(t - 1) * B_ + b];
        float mm = (tokens[t * B_ + b] > 0) ? 1.f : 0.f;
        gl += mm * (trans[cur * KT + prev] + g_feats[((size_t)t * B_ + b) * KT + cur]);
    }
#pragma unroll
    for (int o = 16; o; o >>= 1) gl += __shfl_xor_sync(0xffffffffu, gl, o);
    gl += trans[31 * KT + tags[(T_ - 1) * B_ + b]];

    if (k == 0) g_part[b] = (logz - gl) / (float)lengths[b];
}

__global__ void out_k(float* __restrict__ out) {
    __shared__ float s[B_];
    s[threadIdx.x] = g_part[threadIdx.x];
    __syncthreads();
    for (int o = 32; o; o >>= 1) {
        if (threadIdx.x < o) s[threadIdx.x] += s[threadIdx.x + o];
        __syncthreads();
    }
    if (threadIdx.x == 0) out[0] = s[0];
}

// ---------------- launcher (round-1 verbatim) ----------------
extern "C" void kernel_launch(void* const* d_in, const int* in_sizes, int n_in,
                              void* d_out, int out_size)
{
    const int*   tokens  = (const int*)d_in[0];
    const int*   tags    = (const int*)d_in[1];
    const int*   lengths = (const int*)d_in[2];
    const float* embed   = (const float*)d_in[3];
    const float* wih0    = (const float*)d_in[4];
    const float* whh0    = (const float*)d_in[5];
    const float* b0      = (const float*)d_in[6];
    const float* wih1    = (const float*)d_in[7];
    const float* whh1    = (const float*)d_in[8];
    const float* b1      = (const float*)d_in[9];
    const float* lin_w   = (const float*)d_in[10];
    const float* lin_b   = (const float*)d_in[11];
    const float* trans   = (const float*)d_in[12];
    float* out = (float*)d_out;

    cudaFuncSetAttribute(lstm_rec_k<0>, cudaFuncAttributeMaxDynamicSharedMemorySize, REC_SMEM);
    cudaFuncSetAttribute(lstm_rec_k<1>, cudaFuncAttributeMaxDynamicSharedMemorySize, REC_SMEM);

    const int n4 = T_ * B_ * E_ / 4;
    embed_k<<<(n4 + 255) / 256, 256>>>(tokens, embed);

    gemm_xp_k<0><<<dim3(16, 256, 2), 256>>>(wih0, b0);
    lstm_rec_k<0><<<128, 256, REC_SMEM>>>(whh0);

    gemm_xp_k<1><<<dim3(16, 256, 2), 256>>>(wih1, b1);
    lstm_rec_k<1><<<128, 256, REC_SMEM>>>(whh1);

    feats_k<<<T_ * B_ / 8, 256>>>(lin_w, lin_b);
    crf_k<<<B_, 32>>>(tokens, tags, lengths, trans);
    out_k<<<1, B_>>>(out);
}

// round 7
// speedup vs baseline: 3.8753x; 1.3072x over previous
#include <cuda_runtime.h>
#include <cuda_bf16.h>
#include <cstdint>

#define T_  256
#define B_  64
#define E_  512
#define H_  512
#define KT  32      // num tags
#define G4  2048    // 4*H
#define NEGV -100000.0f

typedef __nv_bfloat16 bf16;

// ---------------- scratch (static device allocations are allowed) ----------------
__device__ float g_x0[(size_t)T_*B_*E_];          // embedded input, tf32-rounded
__device__ float g_xp[(size_t)2*T_*G4*B_];        // input-proj gates  [d][t][g][b]
__device__ float g_x1[(size_t)T_*B_*2*H_];        // layer0 output [tb][1024]
__device__ float g_x2[(size_t)T_*B_*2*H_];        // layer1 output
__device__ float g_h[(size_t)2*H_*B_];            // recurrent h state [d][k][b]
__device__ float g_feats[(size_t)T_*B_*KT];       // emission scores
__device__ float g_part[B_];
__device__ unsigned g_bar_cnt[2];
__device__ unsigned g_bar_gen[2];

// ---------------- helpers ----------------
__device__ __forceinline__ float tf32r(float x) {
    float r;
    asm("cvt.rna.tf32.f32 %0, %1;" : "=f"(r) : "f"(x));
    return r;
}

__device__ __forceinline__ void mma_tf32(float* c,
    float a0, float a1, float a2, float a3, float b0, float b1)
{
    uint32_t A0 = __float_as_uint(a0), A1 = __float_as_uint(a1);
    uint32_t A2 = __float_as_uint(a2), A3 = __float_as_uint(a3);
    uint32_t B0 = __float_as_uint(b0), B1 = __float_as_uint(b1);
    asm volatile(
        "mma.sync.aligned.m16n8k8.row.col.f32.tf32.tf32.f32 "
        "{%0,%1,%2,%3},{%4,%5,%6,%7},{%8,%9},{%0,%1,%2,%3};"
        : "+f"(c[0]), "+f"(c[1]), "+f"(c[2]), "+f"(c[3])
        : "r"(A0), "r"(A1), "r"(A2), "r"(A3), "r"(B0), "r"(B1));
}

__device__ __forceinline__ void mma_bf(float* c, uint32_t a0, uint32_t a1,
                                       uint32_t a2, uint32_t a3,
                                       uint32_t b0, uint32_t b1)
{
    asm volatile(
        "mma.sync.aligned.m16n8k16.row.col.f32.bf16.bf16.f32 "
        "{%0,%1,%2,%3},{%4,%5,%6,%7},{%8,%9},{%0,%1,%2,%3};"
        : "+f"(c[0]), "+f"(c[1]), "+f"(c[2]), "+f"(c[3])
        : "r"(a0), "r"(a1), "r"(a2), "r"(a3), "r"(b0), "r"(b1));
}

__device__ __forceinline__ float sigf(float x) {
    return 1.f / (1.f + __expf(-x));
}

// grid barrier among the 64 blocks of one direction (round-1 proven)
__device__ __forceinline__ void gbarrier(int d) {
    __syncthreads();
    if (threadIdx.x == 0) {
        __threadfence();
        unsigned g = atomicAdd(&g_bar_gen[d], 0u);
        unsigned a = atomicAdd(&g_bar_cnt[d], 1u);
        if (a == 63u) {
            atomicExch(&g_bar_cnt[d], 0u);
            __threadfence();
            atomicExch(&g_bar_gen[d], g + 1u);
        } else {
            while (atomicAdd(&g_bar_gen[d], 0u) == g) { __nanosleep(64); }
        }
        __threadfence();
    }
    __syncthreads();
}

// ---------------- embedding lookup ----------------
__global__ void embed_k(const int* __restrict__ tokens, const float* __restrict__ embed) {
    size_t i = (size_t)blockIdx.x * blockDim.x + threadIdx.x;   // float4 index
    if (i >= (size_t)T_ * B_ * E_ / 4) return;
    size_t el = i * 4;
    size_t tb = el / E_;
    int    e  = (int)(el % E_);
    const float4 v = *(const float4*)(embed + (size_t)tokens[tb] * E_ + e);
    float4 o;
    o.x = tf32r(v.x); o.y = tf32r(v.y); o.z = tf32r(v.z); o.w = tf32r(v.w);
    *(float4*)(g_x0 + el) = o;
}

// ---------------- input projection GEMM (bf16): xp[d][t][g][b] ------------------
// Round-1 structure; ONLY change: smem tiles bf16 (converted in staging) and
// mma.m16n8k16.bf16 inner loop (half the LDS, half the mma count of tf32 k8).
template<int L>
__global__ __launch_bounds__(256) void gemm_xp_k(const float* __restrict__ W,
                                                 const float* __restrict__ bias)
{
    constexpr int KSZ = (L == 0) ? 512 : 1024;
    const float* X = (L == 0) ? g_x0 : g_x1;

    __shared__ __align__(16) bf16 As[128][40];
    __shared__ __align__(16) bf16 Bs[64][40];

    const int d = blockIdx.z, t = blockIdx.y, gbase = blockIdx.x * 128;
    const float* Wd = W + (size_t)d * G4 * KSZ;
    const float* Xt = X + (size_t)t * B_ * KSZ;

    const int tid = threadIdx.x, warp = tid >> 5, lane = tid & 31;
    const int wm = (warp >> 1) * 32, wn = (warp & 1) * 32;
    const int gid = lane >> 2, tig = lane & 3;

    float acc[2][4][4];
#pragma unroll
    for (int a = 0; a < 2; a++)
#pragma unroll
        for (int b = 0; b < 4; b++)
#pragma unroll
            for (int c = 0; c < 4; c++) acc[a][b][c] = 0.f;

    const int r  = tid >> 3;
    const int kv = (tid & 7) * 4;

    for (int k0 = 0; k0 < KSZ; k0 += 32) {
#pragma unroll
        for (int p = 0; p < 4; p++) {
            float4 v = *(const float4*)(Wd + (size_t)(gbase + r + p * 32) * KSZ + k0 + kv);
            __nv_bfloat162 p0 = __floats2bfloat162_rn(v.x, v.y);
            __nv_bfloat162 p1 = __floats2bfloat162_rn(v.z, v.w);
            uint2 pk = make_uint2(*(uint32_t*)&p0, *(uint32_t*)&p1);
            *(uint2*)&As[r + p * 32][kv] = pk;
        }
#pragma unroll
        for (int p = 0; p < 2; p++) {
            float4 v = *(const float4*)(Xt + (size_t)(r + p * 32) * KSZ + k0 + kv);
            __nv_bfloat162 p0 = __floats2bfloat162_rn(v.x, v.y);
            __nv_bfloat162 p1 = __floats2bfloat162_rn(v.z, v.w);
            uint2 pk = make_uint2(*(uint32_t*)&p0, *(uint32_t*)&p1);
            *(uint2*)&Bs[r + p * 32][kv] = pk;
        }
        __syncthreads();
#pragma unroll
        for (int ks = 0; ks < 2; ks++) {
            const int kk = ks * 16 + 2 * tig;
            uint32_t a[2][4];
#pragma unroll
            for (int mt = 0; mt < 2; mt++) {
                int r0 = wm + mt * 16 + gid;
                a[mt][0] = *(const uint32_t*)&As[r0][kk];
                a[mt][1] = *(const uint32_t*)&As[r0 + 8][kk];
                a[mt][2] = *(const uint32_t*)&As[r0][kk + 8];
                a[mt][3] = *(const uint32_t*)&As[r0 + 8][kk + 8];
            }
#pragma unroll
            for (int nt = 0; nt < 4; nt++) {
                int ci = wn + nt * 8 + gid;
                uint32_t b0 = *(const uint32_t*)&Bs[ci][kk];
                uint32_t b1 = *(const uint32_t*)&Bs[ci][kk + 8];
                mma_bf(acc[0][nt], a[0][0], a[0][1], a[0][2], a[0][3], b0, b1);
                mma_bf(acc[1][nt], a[1][0], a[1][1], a[1][2], a[1][3], b0, b1);
            }
        }
        __syncthreads();
    }
    // epilogue: + bias, write xp[d][t][g][b]  (round-1 verbatim)
    float* XP = g_xp + ((size_t)(d * T_ + t) * G4) * B_;
#pragma unroll
    for (int mt = 0; mt < 2; mt++) {
        int r0 = gbase + wm + mt * 16 + gid;
        float bb0 = bias[(size_t)d * G4 + r0];
        float bb1 = bias[(size_t)d * G4 + r0 + 8];
#pragma unroll
        for (int nt = 0; nt < 4; nt++) {
            int c = wn + nt * 8 + tig * 2;
            float2 v0 = make_float2(acc[mt][nt][0] + bb0, acc[mt][nt][1] + bb0);
            float2 v1 = make_float2(acc[mt][nt][2] + bb1, acc[mt][nt][3] + bb1);
            *(float2*)(XP + (size_t)r0 * B_ + c)       = v0;
            *(float2*)(XP + (size_t)(r0 + 8) * B_ + c) = v1;
        }
    }
}

// ---------------- recurrence kernel (round-1 VERBATIM) ----------------
// grid = 128 blocks (0-63 fwd, 64-127 bwd), 256 threads, 8 h-cols per block.
#define REC_SMEM ((32 * 516 + 64 * 68 + 32 * 68) * 4)

template<int L>
__global__ __launch_bounds__(256, 1) void lstm_rec_k(const float* __restrict__ Whh)
{
    float* Xout = (L == 0) ? g_x1 : g_x2;
    extern __shared__ float sm[];
    float* whh_s = sm;                 // [32][516]
    float* h_s   = sm + 32 * 516;      // [64][68]
    float* z_s   = h_s + 64 * 68;      // [32][68]

    const int blk = blockIdx.x;
    const int d = blk >> 6;
    const int jbase = (blk & 63) * 8;
    const int tid = threadIdx.x, warp = tid >> 5, lane = tid & 31;
    const int gid = lane >> 2, tig = lane & 3;
    const int wm = (warp >> 2) * 16, wn = (warp & 3) * 16;

    const float* Wd = Whh + (size_t)d * G4 * H_;

    // load this block's 32 Whh rows (order: q*8 + jl <-> global row q*512+jbase+jl)
    for (int i = tid; i < 32 * 128; i += 256) {
        int m = i >> 7, c4 = (i & 127) * 4;
        int grow = (m >> 3) * 512 + jbase + (m & 7);
        float4 v = *(const float4*)(Wd + (size_t)grow * H_ + c4);
        float4 o; o.x = tf32r(v.x); o.y = tf32r(v.y); o.z = tf32r(v.z); o.w = tf32r(v.w);
        *(float4*)&whh_s[m * 516 + c4] = o;
    }

    // per-thread cell state: pairs (jl, bb) and (jl, bb+1)
    const int p = tid * 2;
    const int jl = p >> 6;
    const int bb = p & 63;
    const int jglob = jbase + jl;
    float cst[2] = {0.f, 0.f};

    g_h[((size_t)d * H_ + jglob) * B_ + bb]     = 0.f;
    g_h[((size_t)d * H_ + jglob) * B_ + bb + 1] = 0.f;

    gbarrier(d);

    for (int s = 0; s < T_; s++) {
        const int t = (d == 0) ? s : (T_ - 1 - s);
        float z[2][4] = {{0.f,0.f,0.f,0.f},{0.f,0.f,0.f,0.f}};

        for (int kc = 0; kc < 8; kc++) {
            // stage 64x64 h chunk
#pragma unroll
            for (int pp = 0; pp < 4; pp++) {
                int kl = (tid >> 4) + pp * 16;
                int b4 = (tid & 15) * 4;
                float4 v = *(const float4*)(g_h + ((size_t)d * H_ + kc * 64 + kl) * B_ + b4);
                *(float4*)&h_s[kl * 68 + b4] = v;
            }
            __syncthreads();
#pragma unroll
            for (int ks = 0; ks < 8; ks++) {
                const int ko = ks * 8;
                const int ar = wm + gid;
                const int kcol = kc * 64 + ko;
                float a0 = whh_s[ar * 516 + kcol + tig];
                float a1 = whh_s[(ar + 8) * 516 + kcol + tig];
                float a2 = whh_s[ar * 516 + kcol + tig + 4];
                float a3 = whh_s[(ar + 8) * 516 + kcol + tig + 4];
#pragma unroll
                for (int nt = 0; nt < 2; nt++) {
                    int nc = wn + nt * 8 + gid;
                    float b0 = h_s[(ko + tig) * 68 + nc];
                    float b1 = h_s[(ko + tig + 4) * 68 + nc];
                    mma_tf32(z[nt], a0, a1, a2, a3, b0, b1);
                }
            }
            __syncthreads();
        }
        // write z fragments to smem
#pragma unroll
        for (int nt = 0; nt < 2; nt++) {
            int cc = wn + nt * 8 + tig * 2;
            *(float2*)&z_s[(wm + gid) * 68 + cc]     = make_float2(z[nt][0], z[nt][1]);
            *(float2*)&z_s[(wm + gid + 8) * 68 + cc] = make_float2(z[nt][2], z[nt][3]);
        }
        __syncthreads();

        // gates + state update for (jl, bb), (jl, bb+1)
        const float* xpb = g_xp + ((size_t)(d * T_ + t) * G4 + jbase + jl) * B_;
#pragma unroll
        for (int u = 0; u < 2; u++) {
            int b = bb + u;
            float zi = z_s[(jl)      * 68 + b] + xpb[0 * H_ * B_ + b];
            float zf = z_s[(8 + jl)  * 68 + b] + xpb[1 * H_ * B_ + b];
            float zg = z_s[(16 + jl) * 68 + b] + xpb[2 * H_ * B_ + b];
            float zo = z_s[(24 + jl) * 68 + b] + xpb[3 * H_ * B_ + b];
            float iv = sigf(zi), fv = sigf(zf), ov = sigf(zo);
            float gv = tanhf(zg);
            cst[u] = fv * cst[u] + iv * gv;
            float h = ov * tanhf(cst[u]);
            float hc = tf32r(h);
            g_h[((size_t)d * H_ + jglob) * B_ + b] = hc;
            Xout[((size_t)t * B_ + b) * (2 * H_) + d * H_ + jglob] = hc;
        }
        gbarrier(d);
    }
}

// ---------------- emission scores (round-1 verbatim) ----------------
__global__ __launch_bounds__(256) void feats_k(const float* __restrict__ lw,
                                               const float* __restrict__ lb)
{
    __shared__ float xs[8][129];
    __shared__ float ws[32][129];
    const int tid = threadIdx.x;
    const int r = tid >> 5, k = tid & 31;
    const size_t tb0 = (size_t)blockIdx.x * 8;
    float acc = 0.f;
    for (int c0 = 0; c0 < 2 * H_; c0 += 128) {
        for (int i = tid; i < 8 * 128; i += 256)
            xs[i >> 7][i & 127] = g_x2[(tb0 + (i >> 7)) * (2 * H_) + c0 + (i & 127)];
        for (int i = tid; i < 32 * 128; i += 256)
            ws[i >> 7][i & 127] = lw[(size_t)(i >> 7) * (2 * H_) + c0 + (i & 127)];
        __syncthreads();
#pragma unroll 16
        for (int kk = 0; kk < 128; kk++) acc += xs[r][kk] * ws[k][kk];
        __syncthreads();
    }
    g_feats[(tb0 + r) * KT + k] = acc + lb[k];
}

// ---------------- CRF (round-1 verbatim) ----------------
__global__ void crf_k(const int* __restrict__ tokens, const int* __restrict__ tags,
                      const int* __restrict__ lengths, const float* __restrict__ trans)
{
    const int b = blockIdx.x;
    const int k = threadIdx.x;              // 0..31
    __shared__ float al[KT];

    float tr[KT];
#pragma unroll
    for (int j = 0; j < KT; j++) tr[j] = trans[k * KT + j];

    al[k] = (k == 30) ? 0.f : NEGV;
    __syncwarp();

    for (int t = 0; t < T_; t++) {
        float m = -3.4e38f;
#pragma unroll
        for (int j = 0; j < KT; j++) m = fmaxf(m, al[j] + tr[j]);
        float ss = 0.f;
#pragma unroll
        for (int j = 0; j < KT; j++) ss += __expf(al[j] + tr[j] - m);
        float nw = m + __logf(ss) + g_feats[((size_t)t * B_ + b) * KT + k];
        int msk = tokens[t * B_ + b] > 0;
        __syncwarp();
        if (msk) al[k] = nw;
        __syncwarp();
    }

    float v = al[k] + trans[31 * KT + k];
    float m = v;
#pragma unroll
    for (int o = 16; o; o >>= 1) m = fmaxf(m, __shfl_xor_sync(0xffffffffu, m, o));
    float e = __expf(v - m);
#pragma unroll
    for (int o = 16; o; o >>= 1) e += __shfl_xor_sync(0xffffffffu, e, o);
    float logz = m + __logf(e);

    float gl = 0.f;
    for (int t = k; t < T_; t += 32) {
        int cur  = tags[t * B_ + b];
        int prev = (t == 0) ? 30 : tags[(t - 1) * B_ + b];
        float mm = (tokens[t * B_ + b] > 0) ? 1.f : 0.f;
        gl += mm * (trans[cur * KT + prev] + g_feats[((size_t)t * B_ + b) * KT + cur]);
    }
#pragma unroll
    for (int o = 16; o; o >>= 1) gl += __shfl_xor_sync(0xffffffffu, gl, o);
    gl += trans[31 * KT + tags[(T_ - 1) * B_ + b]];

    if (k == 0) g_part[b] = (logz - gl) / (float)lengths[b];
}

__global__ void out_k(float* __restrict__ out) {
    __shared__ float s[B_];
    s[threadIdx.x] = g_part[threadIdx.x];
    __syncthreads();
    for (int o = 32; o; o >>= 1) {
        if (threadIdx.x < o) s[threadIdx.x] += s[threadIdx.x + o];
        __syncthreads();
    }
    if (threadIdx.x == 0) out[0] = s[0];
}

// ---------------- launcher (round-1 verbatim) ----------------
extern "C" void kernel_launch(void* const* d_in, const int* in_sizes, int n_in,
                              void* d_out, int out_size)
{
    const int*   tokens  = (const int*)d_in[0];
    const int*   tags    = (const int*)d_in[1];
    const int*   lengths = (const int*)d_in[2];
    const float* embed   = (const float*)d_in[3];
    const float* wih0    = (const float*)d_in[4];
    const float* whh0    = (const float*)d_in[5];
    const float* b0      = (const float*)d_in[6];
    const float* wih1    = (const float*)d_in[7];
    const float* whh1    = (const float*)d_in[8];
    const float* b1      = (const float*)d_in[9];
    const float* lin_w   = (const float*)d_in[10];
    const float* lin_b   = (const float*)d_in[11];
    const float* trans   = (const float*)d_in[12];
    float* out = (float*)d_out;

    cudaFuncSetAttribute(lstm_rec_k<0>, cudaFuncAttributeMaxDynamicSharedMemorySize, REC_SMEM);
    cudaFuncSetAttribute(lstm_rec_k<1>, cudaFuncAttributeMaxDynamicSharedMemorySize, REC_SMEM);

    const int n4 = T_ * B_ * E_ / 4;
    embed_k<<<(n4 + 255) / 256, 256>>>(tokens, embed);

    gemm_xp_k<0><<<dim3(16, 256, 2), 256>>>(wih0, b0);
    lstm_rec_k<0><<<128, 256, REC_SMEM>>>(whh0);

    gemm_xp_k<1><<<dim3(16, 256, 2), 256>>>(wih1, b1);
    lstm_rec_k<1><<<128, 256, REC_SMEM>>>(whh1);

    feats_k<<<T_ * B_ / 8, 256>>>(lin_w, lin_b);
    crf_k<<<B_, 32>>>(tokens, tags, lengths, trans);
    out_k<<<1, B_>>>(out);
}

// round 8
// speedup vs baseline: 5.6463x; 1.4570x over previous
#include <cuda_runtime.h>
#include <cuda_bf16.h>
#include <cstdint>

#define T_  256
#define B_  64
#define E_  512
#define H_  512
#define KT  32      // num tags
#define G4  2048    // 4*H
#define NEGV -100000.0f

typedef __nv_bfloat16 bf16;

// ---------------- scratch (static device allocations are allowed) ----------------
__device__ float g_x0[(size_t)T_*B_*E_];          // embedded input, tf32-rounded
__device__ float g_xp[(size_t)2*T_*G4*B_];        // input-proj gates  [d][t][g][b]
__device__ float g_x1[(size_t)T_*B_*2*H_];        // layer0 output [tb][1024]
__device__ float g_x2[(size_t)T_*B_*2*H_];        // layer1 output
__device__ __align__(16) bf16 g_hbb[(size_t)2*B_*H_];  // recurrent h bf16 [d][b][k]
__device__ float g_feats[(size_t)T_*B_*KT];       // emission scores
__device__ float g_part[B_];
__device__ unsigned g_bar_cnt[2];
__device__ unsigned g_bar_gen[2];

// ---------------- helpers ----------------
__device__ __forceinline__ float tf32r(float x) {
    float r;
    asm("cvt.rna.tf32.f32 %0, %1;" : "=f"(r) : "f"(x));
    return r;
}

__device__ __forceinline__ void mma_bf(float* c, uint32_t a0, uint32_t a1,
                                       uint32_t a2, uint32_t a3,
                                       uint32_t b0, uint32_t b1)
{
    asm volatile(
        "mma.sync.aligned.m16n8k16.row.col.f32.bf16.bf16.f32 "
        "{%0,%1,%2,%3},{%4,%5,%6,%7},{%8,%9},{%0,%1,%2,%3};"
        : "+f"(c[0]), "+f"(c[1]), "+f"(c[2]), "+f"(c[3])
        : "r"(a0), "r"(a1), "r"(a2), "r"(a3), "r"(b0), "r"(b1));
}

__device__ __forceinline__ float sigf(float x) {
    return 1.f / (1.f + __expf(-x));
}

// grid barrier among the 64 blocks of one direction (round-1 proven)
__device__ __forceinline__ void gbarrier(int d) {
    __syncthreads();
    if (threadIdx.x == 0) {
        __threadfence();
        unsigned g = atomicAdd(&g_bar_gen[d], 0u);
        unsigned a = atomicAdd(&g_bar_cnt[d], 1u);
        if (a == 63u) {
            atomicExch(&g_bar_cnt[d], 0u);
            __threadfence();
            atomicExch(&g_bar_gen[d], g + 1u);
        } else {
            while (atomicAdd(&g_bar_gen[d], 0u) == g) { __nanosleep(64); }
        }
        __threadfence();
    }
    __syncthreads();
}

// ---------------- embedding lookup ----------------
__global__ void embed_k(const int* __restrict__ tokens, const float* __restrict__ embed) {
    size_t i = (size_t)blockIdx.x * blockDim.x + threadIdx.x;   // float4 index
    if (i >= (size_t)T_ * B_ * E_ / 4) return;
    size_t el = i * 4;
    size_t tb = el / E_;
    int    e  = (int)(el % E_);
    const float4 v = *(const float4*)(embed + (size_t)tokens[tb] * E_ + e);
    float4 o;
    o.x = tf32r(v.x); o.y = tf32r(v.y); o.z = tf32r(v.z); o.w = tf32r(v.w);
    *(float4*)(g_x0 + el) = o;
}

// ---------------- input projection GEMM (bf16, round-6 verbatim) ----------------
template<int L>
__global__ __launch_bounds__(256) void gemm_xp_k(const float* __restrict__ W,
                                                 const float* __restrict__ bias)
{
    constexpr int KSZ = (L == 0) ? 512 : 1024;
    const float* X = (L == 0) ? g_x0 : g_x1;

    __shared__ __align__(16) bf16 As[128][40];
    __shared__ __align__(16) bf16 Bs[64][40];

    const int d = blockIdx.z, t = blockIdx.y, gbase = blockIdx.x * 128;
    const float* Wd = W + (size_t)d * G4 * KSZ;
    const float* Xt = X + (size_t)t * B_ * KSZ;

    const int tid = threadIdx.x, warp = tid >> 5, lane = tid & 31;
    const int wm = (warp >> 1) * 32, wn = (warp & 1) * 32;
    const int gid = lane >> 2, tig = lane & 3;

    float acc[2][4][4];
#pragma unroll
    for (int a = 0; a < 2; a++)
#pragma unroll
        for (int b = 0; b < 4; b++)
#pragma unroll
            for (int c = 0; c < 4; c++) acc[a][b][c] = 0.f;

    const int r  = tid >> 3;
    const int kv = (tid & 7) * 4;

    for (int k0 = 0; k0 < KSZ; k0 += 32) {
#pragma unroll
        for (int p = 0; p < 4; p++) {
            float4 v = *(const float4*)(Wd + (size_t)(gbase + r + p * 32) * KSZ + k0 + kv);
            __nv_bfloat162 p0 = __floats2bfloat162_rn(v.x, v.y);
            __nv_bfloat162 p1 = __floats2bfloat162_rn(v.z, v.w);
            uint2 pk = make_uint2(*(uint32_t*)&p0, *(uint32_t*)&p1);
            *(uint2*)&As[r + p * 32][kv] = pk;
        }
#pragma unroll
        for (int p = 0; p < 2; p++) {
            float4 v = *(const float4*)(Xt + (size_t)(r + p * 32) * KSZ + k0 + kv);
            __nv_bfloat162 p0 = __floats2bfloat162_rn(v.x, v.y);
            __nv_bfloat162 p1 = __floats2bfloat162_rn(v.z, v.w);
            uint2 pk = make_uint2(*(uint32_t*)&p0, *(uint32_t*)&p1);
            *(uint2*)&Bs[r + p * 32][kv] = pk;
        }
        __syncthreads();
#pragma unroll
        for (int ks = 0; ks < 2; ks++) {
            const int kk = ks * 16 + 2 * tig;
            uint32_t a[2][4];
#pragma unroll
            for (int mt = 0; mt < 2; mt++) {
                int r0 = wm + mt * 16 + gid;
                a[mt][0] = *(const uint32_t*)&As[r0][kk];
                a[mt][1] = *(const uint32_t*)&As[r0 + 8][kk];
                a[mt][2] = *(const uint32_t*)&As[r0][kk + 8];
                a[mt][3] = *(const uint32_t*)&As[r0 + 8][kk + 8];
            }
#pragma unroll
            for (int nt = 0; nt < 4; nt++) {
                int ci = wn + nt * 8 + gid;
                uint32_t b0 = *(const uint32_t*)&Bs[ci][kk];
                uint32_t b1 = *(const uint32_t*)&Bs[ci][kk + 8];
                mma_bf(acc[0][nt], a[0][0], a[0][1], a[0][2], a[0][3], b0, b1);
                mma_bf(acc[1][nt], a[1][0], a[1][1], a[1][2], a[1][3], b0, b1);
            }
        }
        __syncthreads();
    }
    float* XP = g_xp + ((size_t)(d * T_ + t) * G4) * B_;
#pragma unroll
    for (int mt = 0; mt < 2; mt++) {
        int r0 = gbase + wm + mt * 16 + gid;
        float bb0 = bias[(size_t)d * G4 + r0];
        float bb1 = bias[(size_t)d * G4 + r0 + 8];
#pragma unroll
        for (int nt = 0; nt < 4; nt++) {
            int c = wn + nt * 8 + tig * 2;
            float2 v0 = make_float2(acc[mt][nt][0] + bb0, acc[mt][nt][1] + bb0);
            float2 v1 = make_float2(acc[mt][nt][2] + bb1, acc[mt][nt][3] + bb1);
            *(float2*)(XP + (size_t)r0 * B_ + c)       = v0;
            *(float2*)(XP + (size_t)(r0 + 8) * B_ + c) = v1;
        }
    }
}

// ---------------- recurrence kernel (bf16, full-h staging, plain LDG->STS) ------
// grid = 128 blocks (0-63 fwd, 64-127 bwd), 256 threads, 8 h-cols per block.
// smem: whh 32x520 bf16 + h 64x520 bf16 + z 32x68 f32 = 108544 B
#define REC_SMEM ((32 * 520 + 64 * 520) * 2 + 32 * 68 * 4)

template<int L>
__global__ __launch_bounds__(256, 1) void lstm_rec_k(const float* __restrict__ Whh)
{
    float* Xout = (L == 0) ? g_x1 : g_x2;
    extern __shared__ char smraw[];
    bf16*  whh_s = (bf16*)smraw;                     // [32][520]
    bf16*  h_s   = (bf16*)(smraw + 32 * 520 * 2);    // [64][520]
    float* z_s   = (float*)(smraw + (32 + 64) * 520 * 2); // [32][68]

    const int blk = blockIdx.x;
    const int d = blk >> 6;
    const int jbase = (blk & 63) * 8;
    const int tid = threadIdx.x, warp = tid >> 5, lane = tid & 31;
    const int gid = lane >> 2, tig = lane & 3;
    const int wm = (warp >> 2) * 16, wn = (warp & 3) * 16;

    const float* Wd = Whh + (size_t)d * G4 * H_;

    // load + convert this block's 32 Whh rows (local m = q*8+jl <-> q*512+jbase+jl)
    for (int i = tid; i < 32 * 128; i += 256) {
        int m = i >> 7, c4 = (i & 127) * 4;
        int grow = (m >> 3) * 512 + jbase + (m & 7);
        float4 v = *(const float4*)(Wd + (size_t)grow * H_ + c4);
        __nv_bfloat162 p0 = __floats2bfloat162_rn(v.x, v.y);
        __nv_bfloat162 p1 = __floats2bfloat162_rn(v.z, v.w);
        uint2 pk = make_uint2(*(uint32_t*)&p0, *(uint32_t*)&p1);
        *(uint2*)&whh_s[m * 520 + c4] = pk;
    }

    // per-thread cells: b = tid>>2 (0..63), j0 = (tid&3)*2 -> cells (jbase+j0, b),(jbase+j0+1, b)
    const int b  = tid >> 2;
    const int j0 = (tid & 3) * 2;
    float cst[2] = {0.f, 0.f};

    bf16* hrow = g_hbb + ((size_t)d * B_ + b) * H_ + jbase + j0;
    *(__nv_bfloat162*)hrow = __floats2bfloat162_rn(0.f, 0.f);

    gbarrier(d);

    const bf16* hsrc = g_hbb + (size_t)d * B_ * H_;

    for (int s = 0; s < T_; s++) {
        const int t = (d == 0) ? s : (T_ - 1 - s);

        // stage FULL h (64 x 512 bf16) once: 16 uint4 per thread
#pragma unroll
        for (int p = 0; p < 16; p++) {
            int idx = p * 256 + tid;
            int row = idx >> 6;
            int c8  = (idx & 63) * 8;
            *(uint4*)&h_s[row * 520 + c8] = *(const uint4*)(hsrc + (size_t)row * H_ + c8);
        }
        __syncthreads();

        float z[2][4] = {{0.f,0.f,0.f,0.f},{0.f,0.f,0.f,0.f}};
#pragma unroll 8
        for (int ks = 0; ks < 32; ks++) {
            const int kk = ks * 16 + 2 * tig;
            const int ar = wm + gid;
            uint32_t a0 = *(const uint32_t*)&whh_s[ar * 520 + kk];
            uint32_t a1 = *(const uint32_t*)&whh_s[(ar + 8) * 520 + kk];
            uint32_t a2 = *(const uint32_t*)&whh_s[ar * 520 + kk + 8];
            uint32_t a3 = *(const uint32_t*)&whh_s[(ar + 8) * 520 + kk + 8];
#pragma unroll
            for (int nt = 0; nt < 2; nt++) {
                int nc = wn + nt * 8 + gid;
                uint32_t b0 = *(const uint32_t*)&h_s[nc * 520 + kk];
                uint32_t b1 = *(const uint32_t*)&h_s[nc * 520 + kk + 8];
                mma_bf(z[nt], a0, a1, a2, a3, b0, b1);
            }
        }

        // z fragments -> smem (z_s disjoint from h_s/whh_s; sync before reading)
#pragma unroll
        for (int nt = 0; nt < 2; nt++) {
            int cc = wn + nt * 8 + tig * 2;
            *(float2*)&z_s[(wm + gid) * 68 + cc]     = make_float2(z[nt][0], z[nt][1]);
            *(float2*)&z_s[(wm + gid + 8) * 68 + cc] = make_float2(z[nt][2], z[nt][3]);
        }
        __syncthreads();

        // gates + state update for cells (jbase+j0, b), (jbase+j0+1, b)
        const float* xpb = g_xp + ((size_t)(d * T_ + t) * G4 + jbase) * B_;
        float hv[2];
#pragma unroll
        for (int u = 0; u < 2; u++) {
            int j = j0 + u;
            float zi = z_s[(j)      * 68 + b] + xpb[(size_t)(0 * 512 + j) * B_ + b];
            float zf = z_s[(8 + j)  * 68 + b] + xpb[(size_t)(1 * 512 + j) * B_ + b];
            float zg = z_s[(16 + j) * 68 + b] + xpb[(size_t)(2 * 512 + j) * B_ + b];
            float zo = z_s[(24 + j) * 68 + b] + xpb[(size_t)(3 * 512 + j) * B_ + b];
            float iv = sigf(zi), fv = sigf(zf), ov = sigf(zo);
            float gv = tanhf(zg);
            cst[u] = fv * cst[u] + iv * gv;
            hv[u] = ov * tanhf(cst[u]);
        }
        __nv_bfloat162 hb = __floats2bfloat162_rn(hv[0], hv[1]);
        *(__nv_bfloat162*)hrow = hb;
        *(float2*)(Xout + ((size_t)t * B_ + b) * (2 * H_) + d * H_ + jbase + j0) =
            make_float2(__low2float(hb), __high2float(hb));

        gbarrier(d);
    }
}

// ---------------- emission scores (round-1 verbatim) ----------------
__global__ __launch_bounds__(256) void feats_k(const float* __restrict__ lw,
                                               const float* __restrict__ lb)
{
    __shared__ float xs[8][129];
    __shared__ float ws[32][129];
    const int tid = threadIdx.x;
    const int r = tid >> 5, k = tid & 31;
    const size_t tb0 = (size_t)blockIdx.x * 8;
    float acc = 0.f;
    for (int c0 = 0; c0 < 2 * H_; c0 += 128) {
        for (int i = tid; i < 8 * 128; i += 256)
            xs[i >> 7][i & 127] = g_x2[(tb0 + (i >> 7)) * (2 * H_) + c0 + (i & 127)];
        for (int i = tid; i < 32 * 128; i += 256)
            ws[i >> 7][i & 127] = lw[(size_t)(i >> 7) * (2 * H_) + c0 + (i & 127)];
        __syncthreads();
#pragma unroll 16
        for (int kk = 0; kk < 128; kk++) acc += xs[r][kk] * ws[k][kk];
        __syncthreads();
    }
    g_feats[(tb0 + r) * KT + k] = acc + lb[k];
}

// ---------------- CRF (round-1 verbatim) ----------------
__global__ void crf_k(const int* __restrict__ tokens, const int* __restrict__ tags,
                      const int* __restrict__ lengths, const float* __restrict__ trans)
{
    const int b = blockIdx.x;
    const int k = threadIdx.x;              // 0..31
    __shared__ float al[KT];

    float tr[KT];
#pragma unroll
    for (int j = 0; j < KT; j++) tr[j] = trans[k * KT + j];

    al[k] = (k == 30) ? 0.f : NEGV;
    __syncwarp();

    for (int t = 0; t < T_; t++) {
        float m = -3.4e38f;
#pragma unroll
        for (int j = 0; j < KT; j++) m = fmaxf(m, al[j] + tr[j]);
        float ss = 0.f;
#pragma unroll
        for (int j = 0; j < KT; j++) ss += __expf(al[j] + tr[j] - m);
        float nw = m + __logf(ss) + g_feats[((size_t)t * B_ + b) * KT + k];
        int msk = tokens[t * B_ + b] > 0;
        __syncwarp();
        if (msk) al[k] = nw;
        __syncwarp();
    }

    float v = al[k] + trans[31 * KT + k];
    float m = v;
#pragma unroll
    for (int o = 16; o; o >>= 1) m = fmaxf(m, __shfl_xor_sync(0xffffffffu, m, o));
    float e = __expf(v - m);
#pragma unroll
    for (int o = 16; o; o >>= 1) e += __shfl_xor_sync(0xffffffffu, e, o);
    float logz = m + __logf(e);

    float gl = 0.f;
    for (int t = k; t < T_; t += 32) {
        int cur  = tags[t * B_ + b];
        int prev = (t == 0) ? 30 : tags[(t - 1) * B_ + b];
        float mm = (tokens[t * B_ + b] > 0) ? 1.f : 0.f;
        gl += mm * (trans[cur * KT + prev] + g_feats[((size_t)t * B_ + b) * KT + cur]);
    }
#pragma unroll
    for (int o = 16; o; o >>= 1) gl += __shfl_xor_sync(0xffffffffu, gl, o);
    gl += trans[31 * KT + tags[(T_ - 1) * B_ + b]];

    if (k == 0) g_part[b] = (logz - gl) / (float)lengths[b];
}

__global__ void out_k(float* __restrict__ out) {
    __shared__ float s[B_];
    s[threadIdx.x] = g_part[threadIdx.x];
    __syncthreads();
    for (int o = 32; o; o >>= 1) {
        if (threadIdx.x < o) s[threadIdx.x] += s[threadIdx.x + o];
        __syncthreads();
    }
    if (threadIdx.x == 0) out[0] = s[0];
}

// ---------------- launcher ----------------
extern "C" void kernel_launch(void* const* d_in, const int* in_sizes, int n_in,
                              void* d_out, int out_size)
{
    const int*   tokens  = (const int*)d_in[0];
    const int*   tags    = (const int*)d_in[1];
    const int*   lengths = (const int*)d_in[2];
    const float* embed   = (const float*)d_in[3];
    const float* wih0    = (const float*)d_in[4];
    const float* whh0    = (const float*)d_in[5];
    const float* b0      = (const float*)d_in[6];
    const float* wih1    = (const float*)d_in[7];
    const float* whh1    = (const float*)d_in[8];
    const float* b1      = (const float*)d_in[9];
    const float* lin_w   = (const float*)d_in[10];
    const float* lin_b   = (const float*)d_in[11];
    const float* trans   = (const float*)d_in[12];
    float* out = (float*)d_out;

    cudaFuncSetAttribute(lstm_rec_k<0>, cudaFuncAttributeMaxDynamicSharedMemorySize, REC_SMEM);
    cudaFuncSetAttribute(lstm_rec_k<1>, cudaFuncAttributeMaxDynamicSharedMemorySize, REC_SMEM);

    const int n4 = T_ * B_ * E_ / 4;
    embed_k<<<(n4 + 255) / 256, 256>>>(tokens, embed);

    gemm_xp_k<0><<<dim3(16, 256, 2), 256>>>(wih0, b0);
    lstm_rec_k<0><<<128, 256, REC_SMEM>>>(whh0);

    gemm_xp_k<1><<<dim3(16, 256, 2), 256>>>(wih1, b1);
    lstm_rec_k<1><<<128, 256, REC_SMEM>>>(whh1);

    feats_k<<<T_ * B_ / 8, 256>>>(lin_w, lin_b);
    crf_k<<<B_, 32>>>(tokens, tags, lengths, trans);
    out_k<<<1, B_>>>(out);
}

// round 9
// speedup vs baseline: 5.7076x; 1.0109x over previous
#include <cuda_runtime.h>
#include <cuda_bf16.h>
#include <cstdint>

#define T_  256
#define B_  64
#define E_  512
#define H_  512
#define KT  32      // num tags
#define G4  2048    // 4*H
#define NEGV -100000.0f

typedef __nv_bfloat16 bf16;

// ---------------- scratch (static device allocations are allowed) ----------------
__device__ __align__(16) bf16 g_x0b[(size_t)T_*B_*E_];    // embedded input bf16 [tb][512]
__device__ __align__(16) bf16 g_x1b[(size_t)T_*B_*2*H_];  // layer0 out bf16 [tb][1024]
__device__ __align__(16) bf16 g_x2b[(size_t)T_*B_*2*H_];  // layer1 out bf16 [tb][1024]
__device__ __align__(16) bf16 g_wih0b[(size_t)2*G4*E_];   // wih0 bf16
__device__ __align__(16) bf16 g_wih1b[(size_t)2*G4*2*H_]; // wih1 bf16
__device__ float g_xp[(size_t)2*T_*G4*B_];        // input-proj gates fp32 [d][t][g][b]
__device__ __align__(16) bf16 g_hbb[(size_t)2*B_*H_];  // recurrent h bf16 [d][b][k]
__device__ float g_feats[(size_t)T_*B_*KT];       // emission scores
__device__ float g_part[B_];
__device__ unsigned g_bar_cnt[2];
__device__ unsigned g_bar_gen[2];

// ---------------- helpers ----------------
__device__ __forceinline__ void mma_bf(float* c, uint32_t a0, uint32_t a1,
                                       uint32_t a2, uint32_t a3,
                                       uint32_t b0, uint32_t b1)
{
    asm volatile(
        "mma.sync.aligned.m16n8k16.row.col.f32.bf16.bf16.f32 "
        "{%0,%1,%2,%3},{%4,%5,%6,%7},{%8,%9},{%0,%1,%2,%3};"
        : "+f"(c[0]), "+f"(c[1]), "+f"(c[2]), "+f"(c[3])
        : "r"(a0), "r"(a1), "r"(a2), "r"(a3), "r"(b0), "r"(b1));
}

__device__ __forceinline__ float sigf(float x) {
    return 1.f / (1.f + __expf(-x));
}

// grid barrier among the 64 blocks of one direction
__device__ __forceinline__ void gbarrier(int d) {
    __syncthreads();
    if (threadIdx.x == 0) {
        __threadfence();
        unsigned g = atomicAdd(&g_bar_gen[d], 0u);
        unsigned a = atomicAdd(&g_bar_cnt[d], 1u);
        if (a == 63u) {
            atomicExch(&g_bar_cnt[d], 0u);
            __threadfence();
            atomicExch(&g_bar_gen[d], g + 1u);
        } else {
            while (atomicAdd(&g_bar_gen[d], 0u) == g) { __nanosleep(16); }
        }
        __threadfence();
    }
    __syncthreads();
}

// ---------------- weight conversion fp32 -> bf16 (wih only) ----------------
__global__ void cvt_k(const float* __restrict__ wih0, const float* __restrict__ wih1) {
    int i = blockIdx.x * 256 + threadIdx.x;   // float4 index
    const float* s; bf16* dst; int off;
    if (i < 524288)       { s = wih0; dst = g_wih0b; off = i; }
    else if (i < 1572864) { s = wih1; dst = g_wih1b; off = i - 524288; }
    else return;
    float4 v = ((const float4*)s)[off];
    __nv_bfloat162* o = (__nv_bfloat162*)dst + (size_t)off * 2;
    o[0] = __floats2bfloat162_rn(v.x, v.y);
    o[1] = __floats2bfloat162_rn(v.z, v.w);
}

// ---------------- embedding lookup -> bf16 ----------------
__global__ void embed_k(const int* __restrict__ tokens, const float* __restrict__ embed) {
    size_t i = (size_t)blockIdx.x * blockDim.x + threadIdx.x;   // float4 index
    if (i >= (size_t)T_ * B_ * E_ / 4) return;
    size_t el = i * 4;
    size_t tb = el / E_;
    int    e  = (int)(el % E_);
    const float4 v = *(const float4*)(embed + (size_t)tokens[tb] * E_ + e);
    __nv_bfloat162* o = (__nv_bfloat162*)(g_x0b + el);
    o[0] = __floats2bfloat162_rn(v.x, v.y);
    o[1] = __floats2bfloat162_rn(v.z, v.w);
}

// ---------------- input projection GEMM (bf16 in/out staging, zero-cvt) ---------
// Round-6 structure; staging is now raw bf16 uint4 copies (W pre-converted,
// X activations already bf16). mma loop identical to round 6.
template<int L>
__global__ __launch_bounds__(256) void gemm_xp_k(const float* __restrict__ bias)
{
    constexpr int KSZ = (L == 0) ? 512 : 1024;
    const bf16* X = (L == 0) ? g_x0b : g_x1b;
    const bf16* Wb = (L == 0) ? g_wih0b : g_wih1b;

    __shared__ __align__(16) bf16 As[128][40];
    __shared__ __align__(16) bf16 Bs[64][40];

    const int d = blockIdx.z, t = blockIdx.y, gbase = blockIdx.x * 128;
    const bf16* Wd = Wb + (size_t)d * G4 * KSZ;
    const bf16* Xt = X + (size_t)t * B_ * KSZ;

    const int tid = threadIdx.x, warp = tid >> 5, lane = tid & 31;
    const int wm = (warp >> 1) * 32, wn = (warp & 1) * 32;
    const int gid = lane >> 2, tig = lane & 3;

    float acc[2][4][4];
#pragma unroll
    for (int a = 0; a < 2; a++)
#pragma unroll
        for (int b = 0; b < 4; b++)
#pragma unroll
            for (int c = 0; c < 4; c++) acc[a][b][c] = 0.f;

    const int arow = tid >> 2;          // for B tile (64 rows x 4 uint4)
    const int ac8  = (tid & 3) * 8;

    for (int k0 = 0; k0 < KSZ; k0 += 32) {
#pragma unroll
        for (int p = 0; p < 2; p++) {
            int u = tid + p * 256;
            int row = u >> 2, c8 = (u & 3) * 8;
            *(uint4*)&As[row][c8] =
                *(const uint4*)(Wd + (size_t)(gbase + row) * KSZ + k0 + c8);
        }
        *(uint4*)&Bs[arow][ac8] = *(const uint4*)(Xt + (size_t)arow * KSZ + k0 + ac8);
        __syncthreads();
#pragma unroll
        for (int ks = 0; ks < 2; ks++) {
            const int kk = ks * 16 + 2 * tig;
            uint32_t a[2][4];
#pragma unroll
            for (int mt = 0; mt < 2; mt++) {
                int r0 = wm + mt * 16 + gid;
                a[mt][0] = *(const uint32_t*)&As[r0][kk];
                a[mt][1] = *(const uint32_t*)&As[r0 + 8][kk];
                a[mt][2] = *(const uint32_t*)&As[r0][kk + 8];
                a[mt][3] = *(const uint32_t*)&As[r0 + 8][kk + 8];
            }
#pragma unroll
            for (int nt = 0; nt < 4; nt++) {
                int ci = wn + nt * 8 + gid;
                uint32_t b0 = *(const uint32_t*)&Bs[ci][kk];
                uint32_t b1 = *(const uint32_t*)&Bs[ci][kk + 8];
                mma_bf(acc[0][nt], a[0][0], a[0][1], a[0][2], a[0][3], b0, b1);
                mma_bf(acc[1][nt], a[1][0], a[1][1], a[1][2], a[1][3], b0, b1);
            }
        }
        __syncthreads();
    }
    float* XP = g_xp + ((size_t)(d * T_ + t) * G4) * B_;
#pragma unroll
    for (int mt = 0; mt < 2; mt++) {
        int r0 = gbase + wm + mt * 16 + gid;
        float bb0 = bias[(size_t)d * G4 + r0];
        float bb1 = bias[(size_t)d * G4 + r0 + 8];
#pragma unroll
        for (int nt = 0; nt < 4; nt++) {
            int c = wn + nt * 8 + tig * 2;
            float2 v0 = make_float2(acc[mt][nt][0] + bb0, acc[mt][nt][1] + bb0);
            float2 v1 = make_float2(acc[mt][nt][2] + bb1, acc[mt][nt][3] + bb1);
            *(float2*)(XP + (size_t)r0 * B_ + c)       = v0;
            *(float2*)(XP + (size_t)(r0 + 8) * B_ + c) = v1;
        }
    }
}

// ---------------- recurrence kernel (round-7 verbatim, bf16 Xout) ---------------
// grid = 128 blocks (0-63 fwd, 64-127 bwd), 256 threads, 8 h-cols per block.
// smem: whh 32x520 bf16 + h 64x520 bf16 + z 32x68 f32 = 108544 B
#define REC_SMEM ((32 * 520 + 64 * 520) * 2 + 32 * 68 * 4)

template<int L>
__global__ __launch_bounds__(256, 1) void lstm_rec_k(const float* __restrict__ Whh)
{
    bf16* Xout = (L == 0) ? g_x1b : g_x2b;
    extern __shared__ char smraw[];
    bf16*  whh_s = (bf16*)smraw;                     // [32][520]
    bf16*  h_s   = (bf16*)(smraw + 32 * 520 * 2);    // [64][520]
    float* z_s   = (float*)(smraw + (32 + 64) * 520 * 2); // [32][68]

    const int blk = blockIdx.x;
    const int d = blk >> 6;
    const int jbase = (blk & 63) * 8;
    const int tid = threadIdx.x, warp = tid >> 5, lane = tid & 31;
    const int gid = lane >> 2, tig = lane & 3;
    const int wm = (warp >> 2) * 16, wn = (warp & 3) * 16;

    const float* Wd = Whh + (size_t)d * G4 * H_;

    // load + convert this block's 32 Whh rows (local m = q*8+jl <-> q*512+jbase+jl)
    for (int i = tid; i < 32 * 128; i += 256) {
        int m = i >> 7, c4 = (i & 127) * 4;
        int grow = (m >> 3) * 512 + jbase + (m & 7);
        float4 v = *(const float4*)(Wd + (size_t)grow * H_ + c4);
        __nv_bfloat162 p0 = __floats2bfloat162_rn(v.x, v.y);
        __nv_bfloat162 p1 = __floats2bfloat162_rn(v.z, v.w);
        uint2 pk = make_uint2(*(uint32_t*)&p0, *(uint32_t*)&p1);
        *(uint2*)&whh_s[m * 520 + c4] = pk;
    }

    // per-thread cells: b = tid>>2 (0..63), j0 = (tid&3)*2
    const int b  = tid >> 2;
    const int j0 = (tid & 3) * 2;
    float cst[2] = {0.f, 0.f};

    bf16* hrow = g_hbb + ((size_t)d * B_ + b) * H_ + jbase + j0;
    *(__nv_bfloat162*)hrow = __floats2bfloat162_rn(0.f, 0.f);

    gbarrier(d);

    const bf16* hsrc = g_hbb + (size_t)d * B_ * H_;

    for (int s = 0; s < T_; s++) {
        const int t = (d == 0) ? s : (T_ - 1 - s);

        // stage FULL h (64 x 512 bf16) once: 16 uint4 per thread
#pragma unroll
        for (int p = 0; p < 16; p++) {
            int idx = p * 256 + tid;
            int row = idx >> 6;
            int c8  = (idx & 63) * 8;
            *(uint4*)&h_s[row * 520 + c8] = *(const uint4*)(hsrc + (size_t)row * H_ + c8);
        }
        __syncthreads();

        float z[2][4] = {{0.f,0.f,0.f,0.f},{0.f,0.f,0.f,0.f}};
#pragma unroll 8
        for (int ks = 0; ks < 32; ks++) {
            const int kk = ks * 16 + 2 * tig;
            const int ar = wm + gid;
            uint32_t a0 = *(const uint32_t*)&whh_s[ar * 520 + kk];
            uint32_t a1 = *(const uint32_t*)&whh_s[(ar + 8) * 520 + kk];
            uint32_t a2 = *(const uint32_t*)&whh_s[ar * 520 + kk + 8];
            uint32_t a3 = *(const uint32_t*)&whh_s[(ar + 8) * 520 + kk + 8];
#pragma unroll
            for (int nt = 0; nt < 2; nt++) {
                int nc = wn + nt * 8 + gid;
                uint32_t b0 = *(const uint32_t*)&h_s[nc * 520 + kk];
                uint32_t b1 = *(const uint32_t*)&h_s[nc * 520 + kk + 8];
                mma_bf(z[nt], a0, a1, a2, a3, b0, b1);
            }
        }

        // z fragments -> smem
#pragma unroll
        for (int nt = 0; nt < 2; nt++) {
            int cc = wn + nt * 8 + tig * 2;
            *(float2*)&z_s[(wm + gid) * 68 + cc]     = make_float2(z[nt][0], z[nt][1]);
            *(float2*)&z_s[(wm + gid + 8) * 68 + cc] = make_float2(z[nt][2], z[nt][3]);
        }
        __syncthreads();

        // gates + state update for cells (jbase+j0, b), (jbase+j0+1, b)
        const float* xpb = g_xp + ((size_t)(d * T_ + t) * G4 + jbase) * B_;
        float hv[2];
#pragma unroll
        for (int u = 0; u < 2; u++) {
            int j = j0 + u;
            float zi = z_s[(j)      * 68 + b] + xpb[(size_t)(0 * 512 + j) * B_ + b];
            float zf = z_s[(8 + j)  * 68 + b] + xpb[(size_t)(1 * 512 + j) * B_ + b];
            float zg = z_s[(16 + j) * 68 + b] + xpb[(size_t)(2 * 512 + j) * B_ + b];
            float zo = z_s[(24 + j) * 68 + b] + xpb[(size_t)(3 * 512 + j) * B_ + b];
            float iv = sigf(zi), fv = sigf(zf), ov = sigf(zo);
            float gv = tanhf(zg);
            cst[u] = fv * cst[u] + iv * gv;
            hv[u] = ov * tanhf(cst[u]);
        }
        __nv_bfloat162 hb = __floats2bfloat162_rn(hv[0], hv[1]);
        *(__nv_bfloat162*)hrow = hb;
        *(__nv_bfloat162*)(Xout + ((size_t)t * B_ + b) * (2 * H_) + d * H_ + jbase + j0) = hb;

        gbarrier(d);
    }
}

// ---------------- emission scores (reads bf16 x2) ----------------
__global__ __launch_bounds__(256) void feats_k(const float* __restrict__ lw,
                                               const float* __restrict__ lb)
{
    __shared__ float xs[8][129];
    __shared__ float ws[32][129];
    const int tid = threadIdx.x;
    const int r = tid >> 5, k = tid & 31;
    const size_t tb0 = (size_t)blockIdx.x * 8;
    float acc = 0.f;
    for (int c0 = 0; c0 < 2 * H_; c0 += 128) {
        for (int i = tid; i < 8 * 128; i += 256)
            xs[i >> 7][i & 127] =
                __bfloat162float(g_x2b[(tb0 + (i >> 7)) * (2 * H_) + c0 + (i & 127)]);
        for (int i = tid; i < 32 * 128; i += 256)
            ws[i >> 7][i & 127] = lw[(size_t)(i >> 7) * (2 * H_) + c0 + (i & 127)];
        __syncthreads();
#pragma unroll 16
        for (int kk = 0; kk < 128; kk++) acc += xs[r][kk] * ws[k][kk];
        __syncthreads();
    }
    g_feats[(tb0 + r) * KT + k] = acc + lb[k];
}

// ---------------- CRF (round-1 verbatim) ----------------
__global__ void crf_k(const int* __restrict__ tokens, const int* __restrict__ tags,
                      const int* __restrict__ lengths, const float* __restrict__ trans)
{
    const int b = blockIdx.x;
    const int k = threadIdx.x;              // 0..31
    __shared__ float al[KT];

    float tr[KT];
#pragma unroll
    for (int j = 0; j < KT; j++) tr[j] = trans[k * KT + j];

    al[k] = (k == 30) ? 0.f : NEGV;
    __syncwarp();

    for (int t = 0; t < T_; t++) {
        float m = -3.4e38f;
#pragma unroll
        for (int j = 0; j < KT; j++) m = fmaxf(m, al[j] + tr[j]);
        float ss = 0.f;
#pragma unroll
        for (int j = 0; j < KT; j++) ss += __expf(al[j] + tr[j] - m);
        float nw = m + __logf(ss) + g_feats[((size_t)t * B_ + b) * KT + k];
        int msk = tokens[t * B_ + b] > 0;
        __syncwarp();
        if (msk) al[k] = nw;
        __syncwarp();
    }

    float v = al[k] + trans[31 * KT + k];
    float m = v;
#pragma unroll
    for (int o = 16; o; o >>= 1) m = fmaxf(m, __shfl_xor_sync(0xffffffffu, m, o));
    float e = __expf(v - m);
#pragma unroll
    for (int o = 16; o; o >>= 1) e += __shfl_xor_sync(0xffffffffu, e, o);
    float logz = m + __logf(e);

    float gl = 0.f;
    for (int t = k; t < T_; t += 32) {
        int cur  = tags[t * B_ + b];
        int prev = (t == 0) ? 30 : tags[(t - 1) * B_ + b];
        float mm = (tokens[t * B_ + b] > 0) ? 1.f : 0.f;
        gl += mm * (trans[cur * KT + prev] + g_feats[((size_t)t * B_ + b) * KT + cur]);
    }
#pragma unroll
    for (int o = 16; o; o >>= 1) gl += __shfl_xor_sync(0xffffffffu, gl, o);
    gl += trans[31 * KT + tags[(T_ - 1) * B_ + b]];

    if (k == 0) g_part[b] = (logz - gl) / (float)lengths[b];
}

__global__ void out_k(float* __restrict__ out) {
    __shared__ float s[B_];
    s[threadIdx.x] = g_part[threadIdx.x];
    __syncthreads();
    for (int o = 32; o; o >>= 1) {
        if (threadIdx.x < o) s[threadIdx.x] += s[threadIdx.x + o];
        __syncthreads();
    }
    if (threadIdx.x == 0) out[0] = s[0];
}

// ---------------- launcher ----------------
extern "C" void kernel_launch(void* const* d_in, const int* in_sizes, int n_in,
                              void* d_out, int out_size)
{
    const int*   tokens  = (const int*)d_in[0];
    const int*   tags    = (const int*)d_in[1];
    const int*   lengths = (const int*)d_in[2];
    const float* embed   = (const float*)d_in[3];
    const float* wih0    = (const float*)d_in[4];
    const float* whh0    = (const float*)d_in[5];
    const float* b0      = (const float*)d_in[6];
    const float* wih1    = (const float*)d_in[7];
    const float* whh1    = (const float*)d_in[8];
    const float* b1      = (const float*)d_in[9];
    const float* lin_w   = (const float*)d_in[10];
    const float* lin_b   = (const float*)d_in[11];
    const float* trans   = (const float*)d_in[12];
    float* out = (float*)d_out;

    cudaFuncSetAttribute(lstm_rec_k<0>, cudaFuncAttributeMaxDynamicSharedMemorySize, REC_SMEM);
    cudaFuncSetAttribute(lstm_rec_k<1>, cudaFuncAttributeMaxDynamicSharedMemorySize, REC_SMEM);

    cvt_k<<<6144, 256>>>(wih0, wih1);

    const int n4 = T_ * B_ * E_ / 4;
    embed_k<<<(n4 + 255) / 256, 256>>>(tokens, embed);

    gemm_xp_k<0><<<dim3(16, 256, 2), 256>>>(b0);
    lstm_rec_k<0><<<128, 256, REC_SMEM>>>(whh0);

    gemm_xp_k<1><<<dim3(16, 256, 2), 256>>>(b1);
    lstm_rec_k<1><<<128, 256, REC_SMEM>>>(whh1);

    feats_k<<<T_ * B_ / 8, 256>>>(lin_w, lin_b);
    crf_k<<<B_, 32>>>(tokens, tags, lengths, trans);
    out_k<<<1, B_>>>(out);
}